// round 2
// baseline (speedup 1.0000x reference)
#include <cuda_runtime.h>
#include <cuda_bf16.h>
#include <math.h>

// ---------------------------------------------------------------------------
// RGCN: out = sum_r S_r (relu(sum_r S_r x W1_r + b1_r)) W2_r + b2_r
// where S_r = D_in^{-1/2} A_r^T D_out^{-1/2}.
// GEMM-first, single-accumulator scatter:
//   z_r = x @ W1_r ; h = relu(sum_r scatter_r(z_r) + sum_r b1_r)
//   y_r = h @ W2_r ; out = sum_r scatter_r(y_r) + sum_r b2_r
// Edge coefficient folds both norms: c = rsqrt(deg_out[src])*rsqrt(deg_in[dst])
// Index dtype (int32 vs int64) is detected on-device.
// ---------------------------------------------------------------------------

#define NREL 4
#define INF  128
#define HF   128
#define OUTF 64
#define MAXN 100000

__device__ float g_z[(size_t)NREL * MAXN * HF];
__device__ float g_h[(size_t)MAXN * HF];
__device__ float g_y[(size_t)NREL * MAXN * OUTF];
__device__ float g_rs_src[NREL * MAXN];
__device__ float g_rs_dst[NREL * MAXN];
__device__ int   g_idx64;   // 1 if indices are int64, 0 if int32

// ---------------------------------------------------------------------------
// Detect index width: for int64 (nonneg, < 2^31) every odd 32-bit word is 0.
__global__ void detect_idx_kernel(const unsigned int* __restrict__ words,
                                  int n_words) {
    if (threadIdx.x != 0 || blockIdx.x != 0) return;
    int is64 = 1;
    int limit = n_words < 1024 ? n_words : 1024;
    for (int i = 1; i < limit; i += 2) {
        if (words[i] != 0u) { is64 = 0; break; }
    }
    g_idx64 = is64;
}

__device__ __forceinline__ int load_idx(const void* p, size_t i, int is64) {
    return is64 ? (int)((const long long*)p)[i] : ((const int*)p)[i];
}

// ---------------------------------------------------------------------------
__global__ void zero_kernel(float* __restrict__ p, size_t n) {
    size_t i = (size_t)blockIdx.x * blockDim.x + threadIdx.x;
    size_t stride = (size_t)gridDim.x * blockDim.x;
    for (; i < n; i += stride) p[i] = 0.0f;
}

__global__ void degree_kernel(const void* __restrict__ src,
                              const void* __restrict__ dst,
                              float* __restrict__ deg_src,
                              float* __restrict__ deg_dst,
                              int E, int M) {
    int i = blockIdx.x * blockDim.x + threadIdx.x;
    if (i >= NREL * E) return;
    const int is64 = g_idx64;
    int r = i / E;
    int s = load_idx(src, i, is64);
    int d = load_idx(dst, i, is64);
    atomicAdd(&deg_src[r * M + s], 1.0f);
    atomicAdd(&deg_dst[r * M + d], 1.0f);
}

__global__ void rsqrt_kernel(float* __restrict__ a, float* __restrict__ b, int n) {
    int i = blockIdx.x * blockDim.x + threadIdx.x;
    if (i >= n) return;
    a[i] = rsqrtf(fmaxf(a[i], 1.0f));
    b[i] = rsqrtf(fmaxf(b[i], 1.0f));
}

// ---------------------------------------------------------------------------
// C[r][m][n] = sum_k A[m][k] * B[r][k][n],  A:[M,128], B:[NREL,128,NF]
template <int NF>
__global__ __launch_bounds__(256)
void gemm_kernel(const float* __restrict__ A, const float* __restrict__ B,
                 float* __restrict__ C, int M) {
    constexpr int BM = 64, BK = 16;
    constexpr int CPT = NF / 16;
    __shared__ float As[BM][BK + 1];
    __shared__ float Bs[BK][NF + 4];

    const int r    = blockIdx.z;
    const int row0 = blockIdx.x * BM;
    const int tid  = threadIdx.x;
    const int tx   = tid & 15;
    const int ty   = tid >> 4;
    const float* Br = B + (size_t)r * 128 * NF;

    float acc[4][CPT];
#pragma unroll
    for (int i = 0; i < 4; i++)
#pragma unroll
        for (int j = 0; j < CPT; j++) acc[i][j] = 0.0f;

    for (int k0 = 0; k0 < 128; k0 += BK) {
        for (int i = tid; i < BM * BK; i += 256) {
            int rr = i / BK, kk = i % BK;
            int gr = row0 + rr;
            As[rr][kk] = (gr < M) ? A[(size_t)gr * 128 + k0 + kk] : 0.0f;
        }
        for (int i = tid; i < BK * NF; i += 256) {
            int kk = i / NF, nn = i % NF;
            Bs[kk][nn] = Br[(size_t)(k0 + kk) * NF + nn];
        }
        __syncthreads();
#pragma unroll
        for (int k = 0; k < BK; k++) {
            float a[4], b[CPT];
#pragma unroll
            for (int i = 0; i < 4; i++) a[i] = As[ty * 4 + i][k];
#pragma unroll
            for (int j = 0; j < CPT; j++) b[j] = Bs[k][tx * CPT + j];
#pragma unroll
            for (int i = 0; i < 4; i++)
#pragma unroll
                for (int j = 0; j < CPT; j++)
                    acc[i][j] = fmaf(a[i], b[j], acc[i][j]);
        }
        __syncthreads();
    }
#pragma unroll
    for (int i = 0; i < 4; i++) {
        int gr = row0 + ty * 4 + i;
        if (gr < M) {
            float* Cp = C + ((size_t)r * M + gr) * NF + tx * CPT;
#pragma unroll
            for (int j = 0; j < CPT; j++) Cp[j] = acc[i][j];
        }
    }
}

// ---------------------------------------------------------------------------
// out[dst] += c * Z[r][src]   (one warp per edge; NF floats per edge)
template <int NF>
__global__ __launch_bounds__(256)
void scatter_kernel(const float* __restrict__ Z,
                    const void* __restrict__ src,
                    const void* __restrict__ dst,
                    const float* __restrict__ rss,
                    const float* __restrict__ rsd,
                    float* __restrict__ out, int E, int M) {
    const int r    = blockIdx.z;
    const int gw   = blockIdx.x * (blockDim.x >> 5) + (threadIdx.x >> 5);
    const int lane = threadIdx.x & 31;
    if (gw >= E) return;
    const int is64 = g_idx64;
    const size_t ei = (size_t)r * E + gw;
    const int s = load_idx(src, ei, is64);
    const int d = load_idx(dst, ei, is64);
    const float coef = rss[r * M + s] * rsd[r * M + d];
    if (NF == 128) {
        const float4 v = *(const float4*)(Z + ((size_t)r * M + s) * NF + lane * 4);
        float* o = out + (size_t)d * NF + lane * 4;
        atomicAdd(o + 0, coef * v.x);
        atomicAdd(o + 1, coef * v.y);
        atomicAdd(o + 2, coef * v.z);
        atomicAdd(o + 3, coef * v.w);
    } else {
        const float2 v = *(const float2*)(Z + ((size_t)r * M + s) * NF + lane * 2);
        float* o = out + (size_t)d * NF + lane * 2;
        atomicAdd(o + 0, coef * v.x);
        atomicAdd(o + 1, coef * v.y);
    }
}

// ---------------------------------------------------------------------------
__global__ void bias_relu_kernel(float* __restrict__ h,
                                 const float* __restrict__ b1, size_t total) {
    size_t i = (size_t)blockIdx.x * blockDim.x + threadIdx.x;
    if (i >= total) return;
    int f = (int)(i & (HF - 1));
    float b = b1[f] + b1[HF + f] + b1[2 * HF + f] + b1[3 * HF + f];
    h[i] = fmaxf(h[i] + b, 0.0f);
}

__global__ void bias_out_kernel(float* __restrict__ out,
                                const float* __restrict__ b2, size_t total) {
    size_t i = (size_t)blockIdx.x * blockDim.x + threadIdx.x;
    if (i >= total) return;
    int f = (int)(i & (OUTF - 1));
    out[i] += b2[f] + b2[OUTF + f] + b2[2 * OUTF + f] + b2[3 * OUTF + f];
}

// ---------------------------------------------------------------------------
extern "C" void kernel_launch(void* const* d_in, const int* in_sizes, int n_in,
                              void* d_out, int out_size) {
    const float* x    = (const float*)d_in[0];   // [M,128]
    const void*  srcI = d_in[1];                 // [4,E] int32 or int64
    const void*  dstI = d_in[2];                 // [4,E]
    const float* W1   = (const float*)d_in[3];   // [4,128,128]
    const float* b1   = (const float*)d_in[4];   // [4,128]
    const float* W2   = (const float*)d_in[5];   // [4,128,64]
    const float* b2   = (const float*)d_in[6];   // [4,64]
    float*       out  = (float*)d_out;           // [M,64]

    const int M = in_sizes[0] / INF;
    const int E = in_sizes[1] / NREL;

    float *z, *h, *y, *rs_src, *rs_dst;
    cudaGetSymbolAddress((void**)&z, g_z);
    cudaGetSymbolAddress((void**)&h, g_h);
    cudaGetSymbolAddress((void**)&y, g_y);
    cudaGetSymbolAddress((void**)&rs_src, g_rs_src);
    cudaGetSymbolAddress((void**)&rs_dst, g_rs_dst);

    const size_t h_total   = (size_t)M * HF;
    const size_t out_total = (size_t)M * OUTF;

    // detect int32 vs int64 indices (inspects odd 32-bit words)
    detect_idx_kernel<<<1, 32>>>((const unsigned int*)srcI, NREL * E);

    // zero accumulators + degree buffers
    zero_kernel<<<1024, 256>>>(rs_src, (size_t)NREL * M);
    zero_kernel<<<1024, 256>>>(rs_dst, (size_t)NREL * M);
    zero_kernel<<<4096, 256>>>(h, h_total);
    zero_kernel<<<4096, 256>>>(out, out_total);

    // degrees -> rsqrt(max(deg,1))
    degree_kernel<<<(NREL * E + 255) / 256, 256>>>(srcI, dstI, rs_src, rs_dst, E, M);
    rsqrt_kernel<<<(NREL * M + 255) / 256, 256>>>(rs_src, rs_dst, NREL * M);

    // layer 1
    {
        dim3 grid((M + 63) / 64, 1, NREL);
        gemm_kernel<HF><<<grid, 256>>>(x, W1, z, M);
    }
    {
        dim3 grid((E + 7) / 8, 1, NREL);
        scatter_kernel<HF><<<grid, 256>>>(z, srcI, dstI, rs_src, rs_dst, h, E, M);
    }
    bias_relu_kernel<<<(unsigned)((h_total + 255) / 256), 256>>>(h, b1, h_total);

    // layer 2
    {
        dim3 grid((M + 63) / 64, 1, NREL);
        gemm_kernel<OUTF><<<grid, 256>>>(h, W2, y, M);
    }
    {
        dim3 grid((E + 7) / 8, 1, NREL);
        scatter_kernel<OUTF><<<grid, 256>>>(y, srcI, dstI, rs_src, rs_dst, out, E, M);
    }
    bias_out_kernel<<<(unsigned)((out_total + 255) / 256), 256>>>(out, b2, out_total);
}

// round 4
// speedup vs baseline: 1.4075x; 1.4075x over previous
#include <cuda_runtime.h>
#include <cuda_bf16.h>
#include <math.h>
#include <stdint.h>
#include <mma.h>

using namespace nvcuda;

// ---------------------------------------------------------------------------
// RGCN, GEMM-first + single-accumulator scatter.
// GEMMs on tensor cores via wmma tf32 (m16n16k8 HMMA) — tcgen05 is not
// emittable here (harness targets compute_103; tcgen05 is an 'a' feature).
//   z_r = x @ W1_r ; h = relu(sum_r scatter_r(z_r) + sum_r b1_r)
//   y_r = h @ W2_r ; out = sum_r scatter_r(y_r) + sum_r b2_r
// ---------------------------------------------------------------------------

#define NREL 4
#define INF  128
#define HF   128
#define OUTF 64
#define MAXN 100000
#define MAXT ((MAXN + 127) / 128)
#define MAXP (MAXT * 128)            // 100096 padded rows

__device__ float g_z[(size_t)NREL * MAXP * HF];
__device__ float g_h[(size_t)MAXN * HF];
__device__ float g_y[(size_t)NREL * MAXP * OUTF];
__device__ float g_rs_src[NREL * MAXN];
__device__ float g_rs_dst[NREL * MAXN];
__device__ int   g_idx64;

// ---------------------------------------------------------------------------
__global__ void detect_idx_kernel(const unsigned int* __restrict__ words, int n_words) {
    if (threadIdx.x != 0 || blockIdx.x != 0) return;
    int is64 = 1;
    int limit = n_words < 1024 ? n_words : 1024;
    for (int i = 1; i < limit; i += 2)
        if (words[i] != 0u) { is64 = 0; break; }
    g_idx64 = is64;
}
__device__ __forceinline__ int load_idx(const void* p, size_t i, int is64) {
    return is64 ? (int)((const long long*)p)[i] : ((const int*)p)[i];
}

__global__ void zero_kernel(float* __restrict__ p, size_t n) {
    size_t i = (size_t)blockIdx.x * blockDim.x + threadIdx.x;
    size_t st = (size_t)gridDim.x * blockDim.x;
    for (; i < n; i += st) p[i] = 0.0f;
}

__global__ void degree_kernel(const void* __restrict__ src, const void* __restrict__ dst,
                              float* __restrict__ ds, float* __restrict__ dd,
                              int E, int M) {
    int i = blockIdx.x * blockDim.x + threadIdx.x;
    if (i >= NREL * E) return;
    const int is64 = g_idx64;
    int r = i / E;
    atomicAdd(&ds[r * M + load_idx(src, i, is64)], 1.0f);
    atomicAdd(&dd[r * M + load_idx(dst, i, is64)], 1.0f);
}

__global__ void rsqrt_kernel(float* __restrict__ a, float* __restrict__ b, int n) {
    int i = blockIdx.x * blockDim.x + threadIdx.x;
    if (i >= n) return;
    a[i] = rsqrtf(fmaxf(a[i], 1.0f));
    b[i] = rsqrtf(fmaxf(b[i], 1.0f));
}

__global__ void bias_relu_kernel(float* __restrict__ h, const float* __restrict__ b1,
                                 size_t total) {
    size_t i = (size_t)blockIdx.x * blockDim.x + threadIdx.x;
    if (i >= total) return;
    int f = (int)(i & (HF - 1));
    float b = b1[f] + b1[HF + f] + b1[2 * HF + f] + b1[3 * HF + f];
    h[i] = fmaxf(h[i] + b, 0.0f);
}
__global__ void bias_out_kernel(float* __restrict__ out, const float* __restrict__ b2,
                                size_t total) {
    size_t i = (size_t)blockIdx.x * blockDim.x + threadIdx.x;
    if (i >= total) return;
    int f = (int)(i & (OUTF - 1));
    out[i] += b2[f] + b2[OUTF + f] + b2[2 * OUTF + f] + b2[3 * OUTF + f];
}

// ---------------------------------------------------------------------------
// wmma tf32 GEMM: C[r][m][0:NF] = A[m][0:128] @ B[r][0:128][0:NF]
// A fp32 [M x 128] (row-guarded), B fp32 [NREL x 128 x NF], C padded to Mp rows.
// Grid: (tiles, NREL), 256 threads = 8 warps; warp w owns rows [w*16, w*16+16).
// ---------------------------------------------------------------------------
template <int NF>
__global__ __launch_bounds__(256)
void wmma_gemm_kernel(const float* __restrict__ A, const float* __restrict__ B,
                      float* __restrict__ C, int M, int Mp) {
    constexpr int KC = 32;
    constexpr int NFRAG = NF / 16;
    __shared__ float As[128][KC + 4];
    __shared__ float Bs[KC][NF + 4];

    const int r    = blockIdx.y;
    const int row0 = blockIdx.x * 128;
    const int tid  = threadIdx.x;
    const int wid  = tid >> 5;
    const float* Br = B + (size_t)r * 128 * NF;

    wmma::fragment<wmma::accumulator, 16, 16, 8, float> acc[NFRAG];
#pragma unroll
    for (int n = 0; n < NFRAG; n++) wmma::fill_fragment(acc[n], 0.0f);

    for (int k0 = 0; k0 < 128; k0 += KC) {
        // stage A chunk (128 x KC), convert to tf32
#pragma unroll
        for (int i = 0; i < (128 * KC / 4) / 256; i++) {
            int idx = tid + i * 256;          // float4 index
            int rr = idx / (KC / 4);
            int cc = (idx % (KC / 4)) * 4;
            int gr = row0 + rr;
            float4 v = make_float4(0.f, 0.f, 0.f, 0.f);
            if (gr < M) v = *(const float4*)(A + (size_t)gr * 128 + k0 + cc);
            As[rr][cc + 0] = wmma::__float_to_tf32(v.x);
            As[rr][cc + 1] = wmma::__float_to_tf32(v.y);
            As[rr][cc + 2] = wmma::__float_to_tf32(v.z);
            As[rr][cc + 3] = wmma::__float_to_tf32(v.w);
        }
        // stage B chunk (KC x NF), convert to tf32
#pragma unroll
        for (int i = 0; i < (KC * NF / 4) / 256; i++) {
            int idx = tid + i * 256;
            int rr = idx / (NF / 4);
            int cc = (idx % (NF / 4)) * 4;
            float4 v = *(const float4*)(Br + (size_t)(k0 + rr) * NF + cc);
            Bs[rr][cc + 0] = wmma::__float_to_tf32(v.x);
            Bs[rr][cc + 1] = wmma::__float_to_tf32(v.y);
            Bs[rr][cc + 2] = wmma::__float_to_tf32(v.z);
            Bs[rr][cc + 3] = wmma::__float_to_tf32(v.w);
        }
        __syncthreads();
#pragma unroll
        for (int kf = 0; kf < KC / 8; kf++) {
            wmma::fragment<wmma::matrix_a, 16, 16, 8, wmma::precision::tf32,
                           wmma::row_major> a;
            wmma::load_matrix_sync(a, &As[wid * 16][kf * 8], KC + 4);
#pragma unroll
            for (int n = 0; n < NFRAG; n++) {
                wmma::fragment<wmma::matrix_b, 16, 16, 8, wmma::precision::tf32,
                               wmma::row_major> b;
                wmma::load_matrix_sync(b, &Bs[kf * 8][n * 16], NF + 4);
                wmma::mma_sync(acc[n], a, b, acc[n]);
            }
        }
        __syncthreads();
    }

    // epilogue: C is padded to Mp rows per relation, no row guard needed
    float* Crow = C + ((size_t)r * Mp + row0 + wid * 16) * NF;
#pragma unroll
    for (int n = 0; n < NFRAG; n++)
        wmma::store_matrix_sync(Crow + n * 16, acc[n], NF, wmma::mem_row_major);
}

// ---------------------------------------------------------------------------
// scatter: out[dst] += c * Z[r][src]  (one warp per edge; Z padded stride Mp)
// ---------------------------------------------------------------------------
template <int NF>
__global__ __launch_bounds__(256)
void scatter_kernel(const float* __restrict__ Z,
                    const void* __restrict__ src, const void* __restrict__ dst,
                    const float* __restrict__ rss, const float* __restrict__ rsd,
                    float* __restrict__ out, int E, int M, int Mp) {
    const int r = blockIdx.z;
    const int gw = blockIdx.x * (blockDim.x >> 5) + (threadIdx.x >> 5);
    const int lane = threadIdx.x & 31;
    if (gw >= E) return;
    const int is64 = g_idx64;
    const size_t ei = (size_t)r * E + gw;
    const int s = load_idx(src, ei, is64);
    const int d = load_idx(dst, ei, is64);
    const float coef = rss[r * M + s] * rsd[r * M + d];
    if (NF == 128) {
        const float4 v = *(const float4*)(Z + ((size_t)r * Mp + s) * NF + lane * 4);
        float* o = out + (size_t)d * NF + lane * 4;
        atomicAdd(o + 0, coef * v.x);
        atomicAdd(o + 1, coef * v.y);
        atomicAdd(o + 2, coef * v.z);
        atomicAdd(o + 3, coef * v.w);
    } else {
        const float2 v = *(const float2*)(Z + ((size_t)r * Mp + s) * NF + lane * 2);
        float* o = out + (size_t)d * NF + lane * 2;
        atomicAdd(o + 0, coef * v.x);
        atomicAdd(o + 1, coef * v.y);
    }
}

// ---------------------------------------------------------------------------
extern "C" void kernel_launch(void* const* d_in, const int* in_sizes, int n_in,
                              void* d_out, int out_size) {
    const float* x    = (const float*)d_in[0];   // [M,128]
    const void*  srcI = d_in[1];                 // [4,E]
    const void*  dstI = d_in[2];                 // [4,E]
    const float* W1   = (const float*)d_in[3];   // [4,128,128]
    const float* b1   = (const float*)d_in[4];   // [4,128]
    const float* W2   = (const float*)d_in[5];   // [4,128,64]
    const float* b2   = (const float*)d_in[6];   // [4,64]
    float*       out  = (float*)d_out;           // [M,64]

    const int M = in_sizes[0] / INF;
    const int E = in_sizes[1] / NREL;
    const int tiles = (M + 127) / 128;
    const int Mp = tiles * 128;

    float *z, *h, *y, *rs_src, *rs_dst;
    cudaGetSymbolAddress((void**)&z, g_z);
    cudaGetSymbolAddress((void**)&h, g_h);
    cudaGetSymbolAddress((void**)&y, g_y);
    cudaGetSymbolAddress((void**)&rs_src, g_rs_src);
    cudaGetSymbolAddress((void**)&rs_dst, g_rs_dst);

    const size_t h_total = (size_t)M * HF;
    const size_t out_total = (size_t)M * OUTF;

    detect_idx_kernel<<<1, 32>>>((const unsigned int*)srcI, NREL * E);

    zero_kernel<<<1024, 256>>>(rs_src, (size_t)NREL * M);
    zero_kernel<<<1024, 256>>>(rs_dst, (size_t)NREL * M);
    zero_kernel<<<4096, 256>>>(h, h_total);
    zero_kernel<<<4096, 256>>>(out, out_total);

    degree_kernel<<<(NREL * E + 255) / 256, 256>>>(srcI, dstI, rs_src, rs_dst, E, M);
    rsqrt_kernel<<<(NREL * M + 255) / 256, 256>>>(rs_src, rs_dst, NREL * M);

    // layer 1: z_r = x @ W1_r (tf32 HMMA), scatter into h, bias+relu
    {
        dim3 grid(tiles, NREL);
        wmma_gemm_kernel<HF><<<grid, 256>>>(x, W1, z, M, Mp);
    }
    {
        dim3 grid((E + 7) / 8, 1, NREL);
        scatter_kernel<HF><<<grid, 256>>>(z, srcI, dstI, rs_src, rs_dst, h, E, M, Mp);
    }
    bias_relu_kernel<<<(unsigned)((h_total + 255) / 256), 256>>>(h, b1, h_total);

    // layer 2: y_r = h @ W2_r (tf32 HMMA), scatter into out, bias
    {
        dim3 grid(tiles, NREL);
        wmma_gemm_kernel<OUTF><<<grid, 256>>>(h, W2, y, M, Mp);
    }
    {
        dim3 grid((E + 7) / 8, 1, NREL);
        scatter_kernel<OUTF><<<grid, 256>>>(y, srcI, dstI, rs_src, rs_dst, out, E, M, Mp);
    }
    bias_out_kernel<<<(unsigned)((out_total + 255) / 256), 256>>>(out, b2, out_total);
}

// round 5
// speedup vs baseline: 1.9013x; 1.3509x over previous
#include <cuda_runtime.h>
#include <cuda_bf16.h>
#include <math.h>
#include <stdint.h>
#include <mma.h>

using namespace nvcuda;

// ---------------------------------------------------------------------------
// RGCN, GEMM-first + single-accumulator scatter.
//   z_r = x @ W1_r ; h = relu(sum_r scatter_r(z_r) + sum_r b1_r)
//   y_r = h @ W2_r ; out = sum_r scatter_r(y_r) + sum_r b2_r
// GEMMs: wmma tf32 (HMMA). Scatter: float4 vector atomics.
// ---------------------------------------------------------------------------

#define NREL 4
#define INF  128
#define HF   128
#define OUTF 64
#define MAXN 100000
#define MAXT ((MAXN + 127) / 128)
#define MAXP (MAXT * 128)

__device__ float g_z[(size_t)NREL * MAXP * HF];
__device__ float g_h[(size_t)MAXN * HF];
__device__ float g_y[(size_t)NREL * MAXP * OUTF];
__device__ float g_rs_src[NREL * MAXN];
__device__ float g_rs_dst[NREL * MAXN];
__device__ int   g_idx64;

// ---------------------------------------------------------------------------
// Parallel index-width detect: int64 indices (< 2^31) have all-zero odd words.
__global__ void detect_idx_kernel(const unsigned int* __restrict__ words, int n_words) {
    int limit = n_words < 4096 ? n_words : 4096;
    int bad = 0;
    for (int i = 1 + 2 * (int)threadIdx.x; i < limit; i += 2 * (int)blockDim.x)
        bad |= (words[i] != 0u);
    bad = __syncthreads_or(bad);
    if (threadIdx.x == 0) g_idx64 = bad ? 0 : 1;
}
__device__ __forceinline__ int load_idx(const void* p, size_t i, int is64) {
    return is64 ? (int)((const long long*)p)[i] : ((const int*)p)[i];
}

// fused zero of all accumulators (one launch)
__global__ void init_kernel(float* __restrict__ a, size_t na,
                            float* __restrict__ b, size_t nb,
                            float* __restrict__ c, size_t nc,
                            float* __restrict__ d, size_t nd) {
    size_t total = na + nb + nc + nd;
    size_t i = (size_t)blockIdx.x * blockDim.x + threadIdx.x;
    size_t st = (size_t)gridDim.x * blockDim.x;
    for (; i < total; i += st) {
        if (i < na) a[i] = 0.0f;
        else if (i < na + nb) b[i - na] = 0.0f;
        else if (i < na + nb + nc) c[i - na - nb] = 0.0f;
        else d[i - na - nb - nc] = 0.0f;
    }
}

__global__ void degree_kernel(const void* __restrict__ src, const void* __restrict__ dst,
                              float* __restrict__ ds, float* __restrict__ dd,
                              int E, int M) {
    int i = blockIdx.x * blockDim.x + threadIdx.x;
    if (i >= NREL * E) return;
    const int is64 = g_idx64;
    int r = i / E;
    atomicAdd(&ds[r * M + load_idx(src, i, is64)], 1.0f);
    atomicAdd(&dd[r * M + load_idx(dst, i, is64)], 1.0f);
}

__global__ void rsqrt_kernel(float* __restrict__ a, float* __restrict__ b, int n) {
    int i = blockIdx.x * blockDim.x + threadIdx.x;
    if (i >= n) return;
    a[i] = rsqrtf(fmaxf(a[i], 1.0f));
    b[i] = rsqrtf(fmaxf(b[i], 1.0f));
}

__global__ void bias_relu_kernel(float* __restrict__ h, const float* __restrict__ b1,
                                 size_t total) {
    size_t i = (size_t)blockIdx.x * blockDim.x + threadIdx.x;
    if (i >= total) return;
    int f = (int)(i & (HF - 1));
    float b = b1[f] + b1[HF + f] + b1[2 * HF + f] + b1[3 * HF + f];
    h[i] = fmaxf(h[i] + b, 0.0f);
}
__global__ void bias_out_kernel(float* __restrict__ out, const float* __restrict__ b2,
                                size_t total) {
    size_t i = (size_t)blockIdx.x * blockDim.x + threadIdx.x;
    if (i >= total) return;
    int f = (int)(i & (OUTF - 1));
    out[i] += b2[f] + b2[OUTF + f] + b2[2 * OUTF + f] + b2[3 * OUTF + f];
}

// ---------------------------------------------------------------------------
// wmma tf32 GEMM: C[r][m][0:NF] = A[m][0:128] @ B[r][0:128][0:NF]
// ---------------------------------------------------------------------------
template <int NF>
__global__ __launch_bounds__(256)
void wmma_gemm_kernel(const float* __restrict__ A, const float* __restrict__ B,
                      float* __restrict__ C, int M, int Mp) {
    constexpr int KC = 32;
    constexpr int NFRAG = NF / 16;
    __shared__ float As[128][KC + 4];
    __shared__ float Bs[KC][NF + 4];

    const int r    = blockIdx.y;
    const int row0 = blockIdx.x * 128;
    const int tid  = threadIdx.x;
    const int wid  = tid >> 5;
    const float* Br = B + (size_t)r * 128 * NF;

    wmma::fragment<wmma::accumulator, 16, 16, 8, float> acc[NFRAG];
#pragma unroll
    for (int n = 0; n < NFRAG; n++) wmma::fill_fragment(acc[n], 0.0f);

    for (int k0 = 0; k0 < 128; k0 += KC) {
#pragma unroll
        for (int i = 0; i < (128 * KC / 4) / 256; i++) {
            int idx = tid + i * 256;
            int rr = idx / (KC / 4);
            int cc = (idx % (KC / 4)) * 4;
            int gr = row0 + rr;
            float4 v = make_float4(0.f, 0.f, 0.f, 0.f);
            if (gr < M) v = *(const float4*)(A + (size_t)gr * 128 + k0 + cc);
            As[rr][cc + 0] = wmma::__float_to_tf32(v.x);
            As[rr][cc + 1] = wmma::__float_to_tf32(v.y);
            As[rr][cc + 2] = wmma::__float_to_tf32(v.z);
            As[rr][cc + 3] = wmma::__float_to_tf32(v.w);
        }
#pragma unroll
        for (int i = 0; i < (KC * NF / 4) / 256; i++) {
            int idx = tid + i * 256;
            int rr = idx / (NF / 4);
            int cc = (idx % (NF / 4)) * 4;
            float4 v = *(const float4*)(Br + (size_t)(k0 + rr) * NF + cc);
            Bs[rr][cc + 0] = wmma::__float_to_tf32(v.x);
            Bs[rr][cc + 1] = wmma::__float_to_tf32(v.y);
            Bs[rr][cc + 2] = wmma::__float_to_tf32(v.z);
            Bs[rr][cc + 3] = wmma::__float_to_tf32(v.w);
        }
        __syncthreads();
#pragma unroll
        for (int kf = 0; kf < KC / 8; kf++) {
            wmma::fragment<wmma::matrix_a, 16, 16, 8, wmma::precision::tf32,
                           wmma::row_major> a;
            wmma::load_matrix_sync(a, &As[wid * 16][kf * 8], KC + 4);
#pragma unroll
            for (int n = 0; n < NFRAG; n++) {
                wmma::fragment<wmma::matrix_b, 16, 16, 8, wmma::precision::tf32,
                               wmma::row_major> b;
                wmma::load_matrix_sync(b, &Bs[kf * 8][n * 16], NF + 4);
                wmma::mma_sync(acc[n], a, b, acc[n]);
            }
        }
        __syncthreads();
    }

    float* Crow = C + ((size_t)r * Mp + row0 + wid * 16) * NF;
#pragma unroll
    for (int n = 0; n < NFRAG; n++)
        wmma::store_matrix_sync(Crow + n * 16, acc[n], NF, wmma::mem_row_major);
}

// ---------------------------------------------------------------------------
// scatter with float4 vector atomics.
// NF=128: one warp per edge (32 lanes x float4).
// NF=64 : two edges per warp (16 lanes x float4 each).
// ---------------------------------------------------------------------------
__device__ __forceinline__ void vatomic4(float* o, float4 v) {
#if defined(__CUDA_ARCH__) && __CUDA_ARCH__ >= 900
    atomicAdd((float4*)o, v);
#else
    atomicAdd(o + 0, v.x);
    atomicAdd(o + 1, v.y);
    atomicAdd(o + 2, v.z);
    atomicAdd(o + 3, v.w);
#endif
}

__global__ __launch_bounds__(256)
void scatter128_kernel(const float* __restrict__ Z,
                       const void* __restrict__ src, const void* __restrict__ dst,
                       const float* __restrict__ rss, const float* __restrict__ rsd,
                       float* __restrict__ out, int E, int M, int Mp) {
    const int r = blockIdx.z;
    const int gw = blockIdx.x * (blockDim.x >> 5) + (threadIdx.x >> 5);
    const int lane = threadIdx.x & 31;
    if (gw >= E) return;
    const int is64 = g_idx64;
    const size_t ei = (size_t)r * E + gw;
    const int s = load_idx(src, ei, is64);
    const int d = load_idx(dst, ei, is64);
    const float coef = rss[r * M + s] * rsd[r * M + d];
    const float4 v = *(const float4*)(Z + ((size_t)r * Mp + s) * 128 + lane * 4);
    vatomic4(out + (size_t)d * 128 + lane * 4,
             make_float4(coef * v.x, coef * v.y, coef * v.z, coef * v.w));
}

__global__ __launch_bounds__(256)
void scatter64_kernel(const float* __restrict__ Z,
                      const void* __restrict__ src, const void* __restrict__ dst,
                      const float* __restrict__ rss, const float* __restrict__ rsd,
                      float* __restrict__ out, int E, int M, int Mp) {
    const int r = blockIdx.z;
    const int warp = blockIdx.x * (blockDim.x >> 5) + (threadIdx.x >> 5);
    const int lane = threadIdx.x & 31;
    const int sub  = lane >> 4;            // 0 or 1: which edge in this warp
    const int fl   = lane & 15;            // float4 slot within 64 floats
    const int e    = warp * 2 + sub;
    if (e >= E) return;
    const int is64 = g_idx64;
    const size_t ei = (size_t)r * E + e;
    const int s = load_idx(src, ei, is64);
    const int d = load_idx(dst, ei, is64);
    const float coef = rss[r * M + s] * rsd[r * M + d];
    const float4 v = *(const float4*)(Z + ((size_t)r * Mp + s) * 64 + fl * 4);
    vatomic4(out + (size_t)d * 64 + fl * 4,
             make_float4(coef * v.x, coef * v.y, coef * v.z, coef * v.w));
}

// ---------------------------------------------------------------------------
extern "C" void kernel_launch(void* const* d_in, const int* in_sizes, int n_in,
                              void* d_out, int out_size) {
    const float* x    = (const float*)d_in[0];
    const void*  srcI = d_in[1];
    const void*  dstI = d_in[2];
    const float* W1   = (const float*)d_in[3];
    const float* b1   = (const float*)d_in[4];
    const float* W2   = (const float*)d_in[5];
    const float* b2   = (const float*)d_in[6];
    float*       out  = (float*)d_out;

    const int M = in_sizes[0] / INF;
    const int E = in_sizes[1] / NREL;
    const int tiles = (M + 127) / 128;
    const int Mp = tiles * 128;

    float *z, *h, *y, *rs_src, *rs_dst;
    cudaGetSymbolAddress((void**)&z, g_z);
    cudaGetSymbolAddress((void**)&h, g_h);
    cudaGetSymbolAddress((void**)&y, g_y);
    cudaGetSymbolAddress((void**)&rs_src, g_rs_src);
    cudaGetSymbolAddress((void**)&rs_dst, g_rs_dst);

    const size_t h_total = (size_t)M * HF;
    const size_t out_total = (size_t)M * OUTF;

    // launch order chosen so ncu's skip-window lands on wmma_gemm<128>:
    // 1 detect, 2 init, 3 degree, 4 rsqrt, 5 gemm1, 6 scatter1, ...
    detect_idx_kernel<<<1, 256>>>((const unsigned int*)srcI, NREL * E);
    init_kernel<<<4096, 256>>>(rs_src, (size_t)NREL * M,
                               rs_dst, (size_t)NREL * M,
                               h, h_total, out, out_total);
    degree_kernel<<<(NREL * E + 255) / 256, 256>>>(srcI, dstI, rs_src, rs_dst, E, M);
    rsqrt_kernel<<<(NREL * M + 255) / 256, 256>>>(rs_src, rs_dst, NREL * M);

    // layer 1
    {
        dim3 grid(tiles, NREL);
        wmma_gemm_kernel<HF><<<grid, 256>>>(x, W1, z, M, Mp);
    }
    {
        dim3 grid((E + 7) / 8, 1, NREL);
        scatter128_kernel<<<grid, 256>>>(z, srcI, dstI, rs_src, rs_dst, h, E, M, Mp);
    }
    bias_relu_kernel<<<(unsigned)((h_total + 255) / 256), 256>>>(h, b1, h_total);

    // layer 2
    {
        dim3 grid(tiles, NREL);
        wmma_gemm_kernel<OUTF><<<grid, 256>>>(h, W2, y, M, Mp);
    }
    {
        dim3 grid((E + 15) / 16, 1, NREL);   // 2 edges per warp
        scatter64_kernel<<<grid, 256>>>(y, srcI, dstI, rs_src, rs_dst, out, E, M, Mp);
    }
    bias_out_kernel<<<(unsigned)((out_total + 255) / 256), 256>>>(out, b2, out_total);
}

// round 6
// speedup vs baseline: 2.4407x; 1.2837x over previous
#include <cuda_runtime.h>
#include <cuda_bf16.h>
#include <math.h>
#include <stdint.h>
#include <mma.h>

using namespace nvcuda;

// ---------------------------------------------------------------------------
// RGCN, GEMM-first + CSR gather (atomic-free aggregation).
//   z_r = x @ W1_r ; h[d] = relu(sum_{e: dst(e)=d} coef_e * z[rel_e][src_e] + b1sum)
//   y_r = h @ W2_r ; out[d] =   sum_{e: dst(e)=d} coef_e * y[rel_e][src_e] + b2sum
// CSR over all 4 relations combined (same graph both layers).
// GEMMs: wmma tf32, full-K SMEM staging.
// ---------------------------------------------------------------------------

#define NREL 4
#define INF  128
#define HF   128
#define OUTF 64
#define MAXN 100000
#define MAXE 400000
#define MAXT ((MAXN + 127) / 128)
#define MAXP (MAXT * 128)

__device__ float g_z[(size_t)NREL * MAXP * HF];
__device__ float g_y[(size_t)NREL * MAXP * OUTF];
__device__ float g_h[(size_t)MAXN * HF];
__device__ float g_rs_src[NREL * MAXN];
__device__ float g_rs_dst[NREL * MAXN];
__device__ int   g_cnt[MAXN + 1];
__device__ int   g_off[MAXN + 1];
__device__ int   g_cursor[MAXN];
__device__ int   g_epack[NREL * MAXE];
__device__ float g_ecoef[NREL * MAXE];
__device__ int   g_idx64;

__device__ __forceinline__ int load_idx(const void* p, size_t i, int is64) {
    return is64 ? (int)((const long long*)p)[i] : ((const int*)p)[i];
}

// ---------------------------------------------------------------------------
// init: zero degree/count buffers; block 0 additionally detects index width
// (int64 indices < 2^31 have all-zero odd 32-bit words).
__global__ void init_kernel(const unsigned int* __restrict__ words, int n_words,
                            float* __restrict__ rs, float* __restrict__ rd, int nrs,
                            int* __restrict__ cnt, int* __restrict__ cur, int n) {
    if (blockIdx.x == 0) {
        int limit = n_words < 4096 ? n_words : 4096;
        int bad = 0;
        for (int i = 1 + 2 * (int)threadIdx.x; i < limit; i += 2 * (int)blockDim.x)
            bad |= (words[i] != 0u);
        bad = __syncthreads_or(bad);
        if (threadIdx.x == 0) g_idx64 = bad ? 0 : 1;
    }
    int i = blockIdx.x * blockDim.x + threadIdx.x;
    int st = gridDim.x * blockDim.x;
    for (int k = i; k < nrs; k += st) { rs[k] = 0.0f; rd[k] = 0.0f; }
    for (int k = i; k < n; k += st)   { cnt[k] = 0; cur[k] = 0; }
}

// degrees (per relation) + combined per-dst edge counts
__global__ void degree_kernel(const void* __restrict__ src, const void* __restrict__ dst,
                              float* __restrict__ ds, float* __restrict__ dd,
                              int* __restrict__ cnt, int E, int M) {
    int i = blockIdx.x * blockDim.x + threadIdx.x;
    if (i >= NREL * E) return;
    const int is64 = g_idx64;
    int r = i / E;
    int s = load_idx(src, i, is64);
    int d = load_idx(dst, i, is64);
    atomicAdd(&ds[r * M + s], 1.0f);
    atomicAdd(&dd[r * M + d], 1.0f);
    atomicAdd(&cnt[d], 1);
}

__global__ void rsqrt_kernel(float* __restrict__ a, float* __restrict__ b, int n) {
    int i = blockIdx.x * blockDim.x + threadIdx.x;
    if (i >= n) return;
    a[i] = rsqrtf(fmaxf(a[i], 1.0f));
    b[i] = rsqrtf(fmaxf(b[i], 1.0f));
}

// single-CTA exclusive scan (warp shuffles, 1024 threads)
__global__ void scan_kernel(const int* __restrict__ cnt, int* __restrict__ off, int n) {
    __shared__ int wsum[32];
    const int tid = threadIdx.x, lane = tid & 31, wid = tid >> 5;
    int carry = 0;
    for (int base = 0; base < n; base += 1024) {
        int i = base + tid;
        int v = (i < n) ? cnt[i] : 0;
        int s = v;
#pragma unroll
        for (int o = 1; o < 32; o <<= 1) {
            int t = __shfl_up_sync(~0u, s, o);
            if (lane >= o) s += t;
        }
        if (lane == 31) wsum[wid] = s;
        __syncthreads();
        if (wid == 0) {
            int ws = wsum[lane];
#pragma unroll
            for (int o = 1; o < 32; o <<= 1) {
                int t = __shfl_up_sync(~0u, ws, o);
                if (lane >= o) ws += t;
            }
            wsum[lane] = ws;
        }
        __syncthreads();
        int wprefix = (wid > 0) ? wsum[wid - 1] : 0;
        if (i < n) off[i] = carry + s + wprefix - v;
        carry += wsum[31];
        __syncthreads();
    }
    if (tid == 0) off[n] = carry;
}

// fill CSR slots: epack = src | rel<<20, ecoef = rss[src]*rsd[dst]
__global__ void fill_kernel(const void* __restrict__ src, const void* __restrict__ dst,
                            const float* __restrict__ rss, const float* __restrict__ rsd,
                            const int* __restrict__ off, int* __restrict__ cur,
                            int* __restrict__ epack, float* __restrict__ ecoef,
                            int E, int M) {
    int i = blockIdx.x * blockDim.x + threadIdx.x;
    if (i >= NREL * E) return;
    const int is64 = g_idx64;
    int r = i / E;
    int s = load_idx(src, i, is64);
    int d = load_idx(dst, i, is64);
    int pos = off[d] + atomicAdd(&cur[d], 1);
    epack[pos] = s | (r << 20);
    ecoef[pos] = rss[r * M + s] * rsd[r * M + d];
}

// ---------------------------------------------------------------------------
// wmma tf32 GEMM, full-K staging: C[r][m][0:NF] = A[m][:] @ B[r][:][0:NF]
// dynamic smem: As[128][132] + Bs[128][NF+4]
// ---------------------------------------------------------------------------
template <int NF>
__global__ __launch_bounds__(256)
void wmma_gemm_kernel(const float* __restrict__ A, const float* __restrict__ B,
                      float* __restrict__ C, int M, int Mp) {
    constexpr int NFRAG = NF / 16;
    extern __shared__ float sm[];
    float (*As)[132]    = (float(*)[132])sm;
    float (*Bs)[NF + 4] = (float(*)[NF + 4])(sm + 128 * 132);

    const int r    = blockIdx.y;
    const int row0 = blockIdx.x * 128;
    const int tid  = threadIdx.x;
    const int wid  = tid >> 5;
    const float* Br = B + (size_t)r * 128 * NF;

    // stage full A tile (128 x 128) as tf32
#pragma unroll
    for (int i = 0; i < 16; i++) {
        int idx = tid + i * 256;            // float4 slot
        int rr = idx >> 5;
        int cc = (idx & 31) * 4;
        int gr = row0 + rr;
        float4 v = make_float4(0.f, 0.f, 0.f, 0.f);
        if (gr < M) v = *(const float4*)(A + (size_t)gr * 128 + cc);
        As[rr][cc + 0] = wmma::__float_to_tf32(v.x);
        As[rr][cc + 1] = wmma::__float_to_tf32(v.y);
        As[rr][cc + 2] = wmma::__float_to_tf32(v.z);
        As[rr][cc + 3] = wmma::__float_to_tf32(v.w);
    }
    // stage full B (128 x NF) as tf32
#pragma unroll
    for (int i = 0; i < (128 * NF / 4) / 256; i++) {
        int idx = tid + i * 256;
        int rr = idx / (NF / 4);
        int cc = (idx % (NF / 4)) * 4;
        float4 v = *(const float4*)(Br + (size_t)rr * NF + cc);
        Bs[rr][cc + 0] = wmma::__float_to_tf32(v.x);
        Bs[rr][cc + 1] = wmma::__float_to_tf32(v.y);
        Bs[rr][cc + 2] = wmma::__float_to_tf32(v.z);
        Bs[rr][cc + 3] = wmma::__float_to_tf32(v.w);
    }
    __syncthreads();

    wmma::fragment<wmma::accumulator, 16, 16, 8, float> acc[NFRAG];
#pragma unroll
    for (int n = 0; n < NFRAG; n++) wmma::fill_fragment(acc[n], 0.0f);

#pragma unroll
    for (int kf = 0; kf < 16; kf++) {
        wmma::fragment<wmma::matrix_a, 16, 16, 8, wmma::precision::tf32,
                       wmma::row_major> a;
        wmma::load_matrix_sync(a, &As[wid * 16][kf * 8], 132);
#pragma unroll
        for (int n = 0; n < NFRAG; n++) {
            wmma::fragment<wmma::matrix_b, 16, 16, 8, wmma::precision::tf32,
                           wmma::row_major> b;
            wmma::load_matrix_sync(b, &Bs[kf * 8][n * 16], NF + 4);
            wmma::mma_sync(acc[n], a, b, acc[n]);
        }
    }

    float* Crow = C + ((size_t)r * Mp + row0 + wid * 16) * NF;
#pragma unroll
    for (int n = 0; n < NFRAG; n++)
        wmma::store_matrix_sync(Crow + n * 16, acc[n], NF, wmma::mem_row_major);
}

// ---------------------------------------------------------------------------
// gather1: warp per dst node, 128 feats (lane owns float4). h = relu(agg + b1sum)
__global__ __launch_bounds__(256)
void gather1_kernel(const float* __restrict__ Z, const int* __restrict__ off,
                    const int* __restrict__ epack, const float* __restrict__ ecoef,
                    const float* __restrict__ b1, float* __restrict__ h,
                    int M, int Mp) {
    const int d = blockIdx.x * 8 + (threadIdx.x >> 5);
    const int lane = threadIdx.x & 31;
    if (d >= M) return;
    const int e0 = off[d], e1 = off[d + 1];
    float4 acc = make_float4(0.f, 0.f, 0.f, 0.f);
#pragma unroll 2
    for (int e = e0; e < e1; e++) {
        const int p = __ldg(&epack[e]);
        const float c = __ldg(&ecoef[e]);
        const int s = p & 0xFFFFF, r = p >> 20;
        const float4 v = *(const float4*)(Z + ((size_t)r * Mp + s) * 128 + lane * 4);
        acc.x += c * v.x; acc.y += c * v.y; acc.z += c * v.z; acc.w += c * v.w;
    }
    const int f = lane * 4;
    float4 o;
    o.x = fmaxf(acc.x + b1[f+0] + b1[128+f+0] + b1[256+f+0] + b1[384+f+0], 0.f);
    o.y = fmaxf(acc.y + b1[f+1] + b1[128+f+1] + b1[256+f+1] + b1[384+f+1], 0.f);
    o.z = fmaxf(acc.z + b1[f+2] + b1[128+f+2] + b1[256+f+2] + b1[384+f+2], 0.f);
    o.w = fmaxf(acc.w + b1[f+3] + b1[128+f+3] + b1[256+f+3] + b1[384+f+3], 0.f);
    *(float4*)(h + (size_t)d * 128 + f) = o;
}

// gather2: half-warp per dst node, 64 feats (16 lanes x float4). out = agg + b2sum
__global__ __launch_bounds__(256)
void gather2_kernel(const float* __restrict__ Y, const int* __restrict__ off,
                    const int* __restrict__ epack, const float* __restrict__ ecoef,
                    const float* __restrict__ b2, float* __restrict__ out,
                    int M, int Mp) {
    const int warp = blockIdx.x * 8 + (threadIdx.x >> 5);
    const int lane = threadIdx.x & 31;
    const int d = warp * 2 + (lane >> 4);
    const int fl = lane & 15;
    if (d >= M) return;
    const int e0 = off[d], e1 = off[d + 1];
    float4 acc = make_float4(0.f, 0.f, 0.f, 0.f);
#pragma unroll 2
    for (int e = e0; e < e1; e++) {
        const int p = __ldg(&epack[e]);
        const float c = __ldg(&ecoef[e]);
        const int s = p & 0xFFFFF, r = p >> 20;
        const float4 v = *(const float4*)(Y + ((size_t)r * Mp + s) * 64 + fl * 4);
        acc.x += c * v.x; acc.y += c * v.y; acc.z += c * v.z; acc.w += c * v.w;
    }
    const int f = fl * 4;
    float4 o;
    o.x = acc.x + b2[f+0] + b2[64+f+0] + b2[128+f+0] + b2[192+f+0];
    o.y = acc.y + b2[f+1] + b2[64+f+1] + b2[128+f+1] + b2[192+f+1];
    o.z = acc.z + b2[f+2] + b2[64+f+2] + b2[128+f+2] + b2[192+f+2];
    o.w = acc.w + b2[f+3] + b2[64+f+3] + b2[128+f+3] + b2[192+f+3];
    *(float4*)(out + (size_t)d * 64 + f) = o;
}

// ---------------------------------------------------------------------------
extern "C" void kernel_launch(void* const* d_in, const int* in_sizes, int n_in,
                              void* d_out, int out_size) {
    const float* x    = (const float*)d_in[0];
    const void*  srcI = d_in[1];
    const void*  dstI = d_in[2];
    const float* W1   = (const float*)d_in[3];
    const float* b1   = (const float*)d_in[4];
    const float* W2   = (const float*)d_in[5];
    const float* b2   = (const float*)d_in[6];
    float*       out  = (float*)d_out;

    const int M = in_sizes[0] / INF;
    const int E = in_sizes[1] / NREL;
    const int tiles = (M + 127) / 128;
    const int Mp = tiles * 128;

    float *z, *y, *h, *rs_src, *rs_dst, *ecoef;
    int *cnt, *off, *cur, *epack;
    cudaGetSymbolAddress((void**)&z, g_z);
    cudaGetSymbolAddress((void**)&y, g_y);
    cudaGetSymbolAddress((void**)&h, g_h);
    cudaGetSymbolAddress((void**)&rs_src, g_rs_src);
    cudaGetSymbolAddress((void**)&rs_dst, g_rs_dst);
    cudaGetSymbolAddress((void**)&cnt, g_cnt);
    cudaGetSymbolAddress((void**)&off, g_off);
    cudaGetSymbolAddress((void**)&cur, g_cursor);
    cudaGetSymbolAddress((void**)&epack, g_epack);
    cudaGetSymbolAddress((void**)&ecoef, g_ecoef);

    const int SMEM1 = (128 * 132 + 128 * (HF + 4)) * 4;   // 135168
    const int SMEM2 = (128 * 132 + 128 * (OUTF + 4)) * 4; // 102400
    cudaFuncSetAttribute(wmma_gemm_kernel<HF>,
                         cudaFuncAttributeMaxDynamicSharedMemorySize, SMEM1);
    cudaFuncSetAttribute(wmma_gemm_kernel<OUTF>,
                         cudaFuncAttributeMaxDynamicSharedMemorySize, SMEM2);

    // 1 init (+detect)
    init_kernel<<<512, 256>>>((const unsigned int*)srcI, NREL * E,
                              rs_src, rs_dst, NREL * M, cnt, cur, M);
    // 2 degrees + counts
    degree_kernel<<<(NREL * E + 255) / 256, 256>>>(srcI, dstI, rs_src, rs_dst, cnt, E, M);
    // 3 rsqrt
    rsqrt_kernel<<<(NREL * M + 255) / 256, 256>>>(rs_src, rs_dst, NREL * M);
    // 4 scan
    scan_kernel<<<1, 1024>>>(cnt, off, M);
    // 5 fill CSR
    fill_kernel<<<(NREL * E + 255) / 256, 256>>>(srcI, dstI, rs_src, rs_dst,
                                                 off, cur, epack, ecoef, E, M);
    // 6 layer-1 GEMM
    {
        dim3 grid(tiles, NREL);
        wmma_gemm_kernel<HF><<<grid, 256, SMEM1>>>(x, W1, z, M, Mp);
    }
    // 7 layer-1 gather (+bias+relu)
    gather1_kernel<<<(M + 7) / 8, 256>>>(z, off, epack, ecoef, b1, h, M, Mp);
    // 8 layer-2 GEMM
    {
        dim3 grid(tiles, NREL);
        wmma_gemm_kernel<OUTF><<<grid, 256, SMEM2>>>(h, W2, y, M, Mp);
    }
    // 9 layer-2 gather (+bias)
    gather2_kernel<<<(M + 15) / 16, 256>>>(y, off, epack, ecoef, b2, out, M, Mp);
}

// round 7
// speedup vs baseline: 2.6944x; 1.1040x over previous
#include <cuda_runtime.h>
#include <cuda_bf16.h>
#include <math.h>
#include <stdint.h>
#include <mma.h>

using namespace nvcuda;

// ---------------------------------------------------------------------------
// RGCN, GEMM-first + CSR gather (atomic-free aggregation).
//   z_r = x @ W1_r ; h[d] = relu(sum_e coef_e * z[rel_e][src_e] + b1sum)
//   y_r = h @ W2_r ; out[d] =   sum_e coef_e * y[rel_e][src_e] + b2sum
// Multi-block scan for CSR offsets; rsqrt fused into fill.
// ---------------------------------------------------------------------------

#define NREL 4
#define INF  128
#define HF   128
#define OUTF 64
#define MAXN 100000
#define MAXE 400000
#define MAXT ((MAXN + 127) / 128)
#define MAXP (MAXT * 128)
#define SCAN_B 1024

__device__ float g_z[(size_t)NREL * MAXP * HF];
__device__ float g_y[(size_t)NREL * MAXP * OUTF];
__device__ float g_h[(size_t)MAXN * HF];
__device__ float g_deg_src[NREL * MAXN];
__device__ float g_deg_dst[NREL * MAXN];
__device__ int   g_cnt[MAXN + 1];
__device__ int   g_off[MAXN + 1];
__device__ int   g_cursor[MAXN];
__device__ int   g_bsum[128];
__device__ int   g_boff[128];
__device__ int   g_epack[NREL * MAXE];
__device__ float g_ecoef[NREL * MAXE];
__device__ int   g_idx64;

__device__ __forceinline__ int load_idx(const void* p, size_t i, int is64) {
    return is64 ? (int)((const long long*)p)[i] : ((const int*)p)[i];
}

// ---------------------------------------------------------------------------
__global__ void init_kernel(const unsigned int* __restrict__ words, int n_words,
                            float* __restrict__ ds, float* __restrict__ dd, int nrs,
                            int* __restrict__ cnt, int* __restrict__ cur, int n) {
    if (blockIdx.x == 0) {
        int limit = n_words < 4096 ? n_words : 4096;
        int bad = 0;
        for (int i = 1 + 2 * (int)threadIdx.x; i < limit; i += 2 * (int)blockDim.x)
            bad |= (words[i] != 0u);
        bad = __syncthreads_or(bad);
        if (threadIdx.x == 0) g_idx64 = bad ? 0 : 1;
    }
    int i = blockIdx.x * blockDim.x + threadIdx.x;
    int st = gridDim.x * blockDim.x;
    for (int k = i; k < nrs; k += st) { ds[k] = 0.0f; dd[k] = 0.0f; }
    for (int k = i; k < n; k += st)   { cnt[k] = 0; cur[k] = 0; }
}

__global__ void degree_kernel(const void* __restrict__ src, const void* __restrict__ dst,
                              float* __restrict__ ds, float* __restrict__ dd,
                              int* __restrict__ cnt, int E, int M) {
    int i = blockIdx.x * blockDim.x + threadIdx.x;
    if (i >= NREL * E) return;
    const int is64 = g_idx64;
    int r = i / E;
    int s = load_idx(src, i, is64);
    int d = load_idx(dst, i, is64);
    atomicAdd(&ds[r * M + s], 1.0f);
    atomicAdd(&dd[r * M + d], 1.0f);
    atomicAdd(&cnt[d], 1);
}

// ---------------------------------------------------------------------------
// 3-pass multi-block exclusive scan of cnt[0..n) -> off[0..n]
__device__ __forceinline__ int block_incl_scan(int v, int* wsum) {
    const int lane = threadIdx.x & 31, wid = threadIdx.x >> 5;
    int s = v;
#pragma unroll
    for (int o = 1; o < 32; o <<= 1) {
        int t = __shfl_up_sync(~0u, s, o);
        if (lane >= o) s += t;
    }
    if (lane == 31) wsum[wid] = s;
    __syncthreads();
    if (wid == 0) {
        int ws = (lane < (SCAN_B / 32)) ? wsum[lane] : 0;
#pragma unroll
        for (int o = 1; o < 32; o <<= 1) {
            int t = __shfl_up_sync(~0u, ws, o);
            if (lane >= o) ws += t;
        }
        wsum[lane] = ws;
    }
    __syncthreads();
    return s + (wid > 0 ? wsum[wid - 1] : 0);
}

__global__ void scanA_kernel(const int* __restrict__ cnt, int* __restrict__ bsum, int n) {
    __shared__ int wsum[32];
    int i = blockIdx.x * SCAN_B + threadIdx.x;
    int v = (i < n) ? cnt[i] : 0;
    int s = block_incl_scan(v, wsum);
    if (threadIdx.x == SCAN_B - 1) bsum[blockIdx.x] = s;
}

__global__ void scanB_kernel(const int* __restrict__ bsum, int* __restrict__ boff,
                             int* __restrict__ off, int nb, int n) {
    // one warp, loop with carry (nb <= 128)
    const int lane = threadIdx.x;
    int carry = 0;
    for (int base = 0; base < nb; base += 32) {
        int i = base + lane;
        int v = (i < nb) ? bsum[i] : 0;
        int s = v;
#pragma unroll
        for (int o = 1; o < 32; o <<= 1) {
            int t = __shfl_up_sync(~0u, s, o);
            if (lane >= o) s += t;
        }
        if (i < nb) boff[i] = carry + s - v;
        carry += __shfl_sync(~0u, s, 31);
    }
    if (lane == 0) off[n] = carry;
}

__global__ void scanC_kernel(const int* __restrict__ cnt, const int* __restrict__ boff,
                             int* __restrict__ off, int n) {
    __shared__ int wsum[32];
    int i = blockIdx.x * SCAN_B + threadIdx.x;
    int v = (i < n) ? cnt[i] : 0;
    int s = block_incl_scan(v, wsum);
    if (i < n) off[i] = boff[blockIdx.x] + s - v;
}

// ---------------------------------------------------------------------------
// fill CSR slots: epack = src | rel<<20, ecoef = rsqrt(ds[src])*rsqrt(dd[dst])
__global__ void fill_kernel(const void* __restrict__ src, const void* __restrict__ dst,
                            const float* __restrict__ ds, const float* __restrict__ dd,
                            const int* __restrict__ off, int* __restrict__ cur,
                            int* __restrict__ epack, float* __restrict__ ecoef,
                            int E, int M) {
    int i = blockIdx.x * blockDim.x + threadIdx.x;
    if (i >= NREL * E) return;
    const int is64 = g_idx64;
    int r = i / E;
    int s = load_idx(src, i, is64);
    int d = load_idx(dst, i, is64);
    int pos = off[d] + atomicAdd(&cur[d], 1);
    epack[pos] = s | (r << 20);
    ecoef[pos] = rsqrtf(fmaxf(ds[r * M + s], 1.0f)) * rsqrtf(fmaxf(dd[r * M + d], 1.0f));
}

// ---------------------------------------------------------------------------
// wmma tf32 GEMM, full-K staging
// ---------------------------------------------------------------------------
template <int NF>
__global__ __launch_bounds__(256)
void wmma_gemm_kernel(const float* __restrict__ A, const float* __restrict__ B,
                      float* __restrict__ C, int M, int Mp) {
    constexpr int NFRAG = NF / 16;
    extern __shared__ float sm[];
    float (*As)[132]    = (float(*)[132])sm;
    float (*Bs)[NF + 4] = (float(*)[NF + 4])(sm + 128 * 132);

    const int r    = blockIdx.y;
    const int row0 = blockIdx.x * 128;
    const int tid  = threadIdx.x;
    const int wid  = tid >> 5;
    const float* Br = B + (size_t)r * 128 * NF;

#pragma unroll
    for (int i = 0; i < 16; i++) {
        int idx = tid + i * 256;
        int rr = idx >> 5;
        int cc = (idx & 31) * 4;
        int gr = row0 + rr;
        float4 v = make_float4(0.f, 0.f, 0.f, 0.f);
        if (gr < M) v = *(const float4*)(A + (size_t)gr * 128 + cc);
        As[rr][cc + 0] = wmma::__float_to_tf32(v.x);
        As[rr][cc + 1] = wmma::__float_to_tf32(v.y);
        As[rr][cc + 2] = wmma::__float_to_tf32(v.z);
        As[rr][cc + 3] = wmma::__float_to_tf32(v.w);
    }
#pragma unroll
    for (int i = 0; i < (128 * NF / 4) / 256; i++) {
        int idx = tid + i * 256;
        int rr = idx / (NF / 4);
        int cc = (idx % (NF / 4)) * 4;
        float4 v = *(const float4*)(Br + (size_t)rr * NF + cc);
        Bs[rr][cc + 0] = wmma::__float_to_tf32(v.x);
        Bs[rr][cc + 1] = wmma::__float_to_tf32(v.y);
        Bs[rr][cc + 2] = wmma::__float_to_tf32(v.z);
        Bs[rr][cc + 3] = wmma::__float_to_tf32(v.w);
    }
    __syncthreads();

    wmma::fragment<wmma::accumulator, 16, 16, 8, float> acc[NFRAG];
#pragma unroll
    for (int n = 0; n < NFRAG; n++) wmma::fill_fragment(acc[n], 0.0f);

#pragma unroll
    for (int kf = 0; kf < 16; kf++) {
        wmma::fragment<wmma::matrix_a, 16, 16, 8, wmma::precision::tf32,
                       wmma::row_major> a;
        wmma::load_matrix_sync(a, &As[wid * 16][kf * 8], 132);
#pragma unroll
        for (int n = 0; n < NFRAG; n++) {
            wmma::fragment<wmma::matrix_b, 16, 16, 8, wmma::precision::tf32,
                           wmma::row_major> b;
            wmma::load_matrix_sync(b, &Bs[kf * 8][n * 16], NF + 4);
            wmma::mma_sync(acc[n], a, b, acc[n]);
        }
    }

    float* Crow = C + ((size_t)r * Mp + row0 + wid * 16) * NF;
#pragma unroll
    for (int n = 0; n < NFRAG; n++)
        wmma::store_matrix_sync(Crow + n * 16, acc[n], NF, wmma::mem_row_major);
}

// ---------------------------------------------------------------------------
// gather1: warp per dst, 128 feats; h = relu(agg + b1sum)
__global__ __launch_bounds__(256)
void gather1_kernel(const float* __restrict__ Z, const int* __restrict__ off,
                    const int* __restrict__ epack, const float* __restrict__ ecoef,
                    const float* __restrict__ b1, float* __restrict__ h,
                    int M, int Mp) {
    const int d = blockIdx.x * 8 + (threadIdx.x >> 5);
    const int lane = threadIdx.x & 31;
    if (d >= M) return;
    const int e0 = off[d], e1 = off[d + 1];
    float4 acc = make_float4(0.f, 0.f, 0.f, 0.f);
#pragma unroll 4
    for (int e = e0; e < e1; e++) {
        const int p = __ldg(&epack[e]);
        const float c = __ldg(&ecoef[e]);
        const int s = p & 0xFFFFF, r = p >> 20;
        const float4 v = *(const float4*)(Z + ((size_t)r * Mp + s) * 128 + lane * 4);
        acc.x += c * v.x; acc.y += c * v.y; acc.z += c * v.z; acc.w += c * v.w;
    }
    const int f = lane * 4;
    float4 o;
    o.x = fmaxf(acc.x + b1[f+0] + b1[128+f+0] + b1[256+f+0] + b1[384+f+0], 0.f);
    o.y = fmaxf(acc.y + b1[f+1] + b1[128+f+1] + b1[256+f+1] + b1[384+f+1], 0.f);
    o.z = fmaxf(acc.z + b1[f+2] + b1[128+f+2] + b1[256+f+2] + b1[384+f+2], 0.f);
    o.w = fmaxf(acc.w + b1[f+3] + b1[128+f+3] + b1[256+f+3] + b1[384+f+3], 0.f);
    *(float4*)(h + (size_t)d * 128 + f) = o;
}

// gather2: half-warp per dst, 64 feats; out = agg + b2sum
__global__ __launch_bounds__(256)
void gather2_kernel(const float* __restrict__ Y, const int* __restrict__ off,
                    const int* __restrict__ epack, const float* __restrict__ ecoef,
                    const float* __restrict__ b2, float* __restrict__ out,
                    int M, int Mp) {
    const int warp = blockIdx.x * 8 + (threadIdx.x >> 5);
    const int lane = threadIdx.x & 31;
    const int d = warp * 2 + (lane >> 4);
    const int fl = lane & 15;
    if (d >= M) return;
    const int e0 = off[d], e1 = off[d + 1];
    float4 acc = make_float4(0.f, 0.f, 0.f, 0.f);
#pragma unroll 4
    for (int e = e0; e < e1; e++) {
        const int p = __ldg(&epack[e]);
        const float c = __ldg(&ecoef[e]);
        const int s = p & 0xFFFFF, r = p >> 20;
        const float4 v = *(const float4*)(Y + ((size_t)r * Mp + s) * 64 + fl * 4);
        acc.x += c * v.x; acc.y += c * v.y; acc.z += c * v.z; acc.w += c * v.w;
    }
    const int f = fl * 4;
    float4 o;
    o.x = acc.x + b2[f+0] + b2[64+f+0] + b2[128+f+0] + b2[192+f+0];
    o.y = acc.y + b2[f+1] + b2[64+f+1] + b2[128+f+1] + b2[192+f+1];
    o.z = acc.z + b2[f+2] + b2[64+f+2] + b2[128+f+2] + b2[192+f+2];
    o.w = acc.w + b2[f+3] + b2[64+f+3] + b2[128+f+3] + b2[192+f+3];
    *(float4*)(out + (size_t)d * 64 + f) = o;
}

// ---------------------------------------------------------------------------
extern "C" void kernel_launch(void* const* d_in, const int* in_sizes, int n_in,
                              void* d_out, int out_size) {
    const float* x    = (const float*)d_in[0];
    const void*  srcI = d_in[1];
    const void*  dstI = d_in[2];
    const float* W1   = (const float*)d_in[3];
    const float* b1   = (const float*)d_in[4];
    const float* W2   = (const float*)d_in[5];
    const float* b2   = (const float*)d_in[6];
    float*       out  = (float*)d_out;

    const int M = in_sizes[0] / INF;
    const int E = in_sizes[1] / NREL;
    const int tiles = (M + 127) / 128;
    const int Mp = tiles * 128;
    const int NB = (M + SCAN_B - 1) / SCAN_B;

    float *z, *y, *h, *ds, *dd, *ecoef;
    int *cnt, *off, *cur, *epack, *bsum, *boff;
    cudaGetSymbolAddress((void**)&z, g_z);
    cudaGetSymbolAddress((void**)&y, g_y);
    cudaGetSymbolAddress((void**)&h, g_h);
    cudaGetSymbolAddress((void**)&ds, g_deg_src);
    cudaGetSymbolAddress((void**)&dd, g_deg_dst);
    cudaGetSymbolAddress((void**)&cnt, g_cnt);
    cudaGetSymbolAddress((void**)&off, g_off);
    cudaGetSymbolAddress((void**)&cur, g_cursor);
    cudaGetSymbolAddress((void**)&epack, g_epack);
    cudaGetSymbolAddress((void**)&ecoef, g_ecoef);
    cudaGetSymbolAddress((void**)&bsum, g_bsum);
    cudaGetSymbolAddress((void**)&boff, g_boff);

    const int SMEM1 = (128 * 132 + 128 * (HF + 4)) * 4;
    const int SMEM2 = (128 * 132 + 128 * (OUTF + 4)) * 4;
    cudaFuncSetAttribute(wmma_gemm_kernel<HF>,
                         cudaFuncAttributeMaxDynamicSharedMemorySize, SMEM1);
    cudaFuncSetAttribute(wmma_gemm_kernel<OUTF>,
                         cudaFuncAttributeMaxDynamicSharedMemorySize, SMEM2);

    // 1 init (+detect)
    init_kernel<<<512, 256>>>((const unsigned int*)srcI, NREL * E,
                              ds, dd, NREL * M, cnt, cur, M);
    // 2 degrees + counts
    degree_kernel<<<(NREL * E + 255) / 256, 256>>>(srcI, dstI, ds, dd, cnt, E, M);
    // 3-5 multi-block scan
    scanA_kernel<<<NB, SCAN_B>>>(cnt, bsum, M);
    scanB_kernel<<<1, 32>>>(bsum, boff, off, NB, M);
    scanC_kernel<<<NB, SCAN_B>>>(cnt, boff, off, M);
    // 6 layer-1 GEMM  (ncu -s 5 -c 1 lands here)
    {
        dim3 grid(tiles, NREL);
        wmma_gemm_kernel<HF><<<grid, 256, SMEM1>>>(x, W1, z, M, Mp);
    }
    // 7 fill CSR (rsqrt fused)
    fill_kernel<<<(NREL * E + 255) / 256, 256>>>(srcI, dstI, ds, dd,
                                                 off, cur, epack, ecoef, E, M);
    // 8 layer-1 gather (+bias+relu)
    gather1_kernel<<<(M + 7) / 8, 256>>>(z, off, epack, ecoef, b1, h, M, Mp);
    // 9 layer-2 GEMM
    {
        dim3 grid(tiles, NREL);
        wmma_gemm_kernel<OUTF><<<grid, 256, SMEM2>>>(h, W2, y, M, Mp);
    }
    // 10 layer-2 gather (+bias)
    gather2_kernel<<<(M + 15) / 16, 256>>>(y, off, epack, ecoef, b2, out, M, Mp);
}